// round 1
// baseline (speedup 1.0000x reference)
#include <cuda_runtime.h>
#include <math.h>

#define Cc   64
#define Hh   64
#define Ww   64
#define BSz  4
#define HS   256
#define WS   256
#define KK   8
#define NPH  16

// ---- device scratch (no allocations allowed) ----
__device__ float g_mean[Cc];
// layouts interleave (chi, half, phase) so warp LDS accesses are conflict-free
__device__ __align__(16) float g_Wcm[KK * 32 * 2 * NPH];   // ((k*32+chi)*2+half)*16 + p
__device__ __align__(16) float g_Wem[32 * KK * 2 * NPH];   // ((chi*8+k)*2+half)*16 + p
__device__ float4 g_samp[32 * 2 * NPH];                    // (chi*2+half)*16 + p : {Y0,X0,wy,wx}

// ---------------------------------------------------------------------------
// Kernel A: per-channel mean of x over (b, h, w)
// ---------------------------------------------------------------------------
__global__ void mean_kernel(const float* __restrict__ x) {
    int ch = blockIdx.x;
    int t  = threadIdx.x;
    float s = 0.f;
    const float* base = x + (size_t)ch * Hh * Ww;
    for (int b = 0; b < BSz; ++b) {
        const float* p = base + (size_t)b * Cc * Hh * Ww;
        for (int idx = t; idx < Hh * Ww; idx += 256) s += p[idx];
    }
    __shared__ float red[8];
#pragma unroll
    for (int o = 16; o > 0; o >>= 1) s += __shfl_xor_sync(0xffffffffu, s, o);
    if ((t & 31) == 0) red[t >> 5] = s;
    __syncthreads();
    if (t == 0) {
        float tot = 0.f;
#pragma unroll
        for (int w = 0; w < 8; ++w) tot += red[w];
        g_mean[ch] = tot * (1.f / (float)(BSz * Hh * Ww));
    }
}

__device__ __forceinline__ float sigmoidf_(float v) { return 1.f / (1.f + expf(-v)); }

// ---------------------------------------------------------------------------
// Kernel B: per-phase meta network (16 blocks, 64 threads).
// Everything (emb, offsets, routing, expert-mixed matrices) depends only on
// the 16 spatial phases (i%4, j%4).
// ---------------------------------------------------------------------------
__global__ void phase_kernel(
    const float* __restrict__ wc,  const float* __restrict__ we,
    const float* __restrict__ Wb1, const float* __restrict__ bb1,
    const float* __restrict__ Wb2, const float* __restrict__ bb2,
    const float* __restrict__ Wr1, const float* __restrict__ br1,
    const float* __restrict__ Wr2, const float* __restrict__ br2,
    const float* __restrict__ Wq1, const float* __restrict__ bq1,
    const float* __restrict__ Wq2, const float* __restrict__ bq2,
    const float* __restrict__ Wq3, const float* __restrict__ bq3,
    const float* __restrict__ Wo1, const float* __restrict__ bo1,
    const float* __restrict__ Wo2, const float* __restrict__ bo2,
    const float* __restrict__ Wo3, const float* __restrict__ bo3)
{
    int p = blockIdx.x, pi = p >> 2, pj = p & 3;
    int t = threadIdx.x;  // 0..63
    float m2 = (pi + 0.5f) * 0.25f - 0.5f;   // coor_h for this phase row
    float m3 = (pj + 0.5f) * 0.25f - 0.5f;   // coor_w

    __shared__ float s_a[64][4];  // t1, then reused as v1
    __shared__ float s_b[64][4];  // emb
    __shared__ float s_r[4], s_q1[64], s_q2[64], s_rw[4];

    // ---- body layer 1: t1[o][f] = relu(Wb1 @ inp + bb1)
    // inp[ch][0] = mean[ch]; inp[ch][1]=0.25; inp[ch][2]=m2; inp[ch][3]=m3
    float sm = 0.f, sr = 0.f;
    for (int ch = 0; ch < 64; ++ch) {
        float wv = Wb1[t * 64 + ch];
        sm += wv * g_mean[ch];
        sr += wv;
    }
    {
        float b1 = bb1[t];
        s_a[t][0] = fmaxf(sm + b1, 0.f);
        s_a[t][1] = fmaxf(0.25f * sr + b1, 0.f);
        s_a[t][2] = fmaxf(m2 * sr + b1, 0.f);
        s_a[t][3] = fmaxf(m3 * sr + b1, 0.f);
    }
    __syncthreads();

    // ---- body layer 2: emb
    {
        float b2 = bb2[t];
        float a0 = b2, a1 = b2, a2 = b2, a3 = b2;
        for (int ch = 0; ch < 64; ++ch) {
            float wv = Wb2[t * 64 + ch];
            a0 += wv * s_a[ch][0]; a1 += wv * s_a[ch][1];
            a2 += wv * s_a[ch][2]; a3 += wv * s_a[ch][3];
        }
        s_b[t][0] = fmaxf(a0, 0.f); s_b[t][1] = fmaxf(a1, 0.f);
        s_b[t][2] = fmaxf(a2, 0.f); s_b[t][3] = fmaxf(a3, 0.f);
    }
    __syncthreads();

    // ---- offset head (thread t = channel): 4 -> 64 -> 64 -> 2
    {
        float e0 = s_b[t][0], e1 = s_b[t][1], e2 = s_b[t][2], e3 = s_b[t][3];
        float u1[64], u2[64];
        for (int jn = 0; jn < 64; ++jn)
            u1[jn] = fmaxf(Wo1[jn * 4 + 0] * e0 + Wo1[jn * 4 + 1] * e1 +
                           Wo1[jn * 4 + 2] * e2 + Wo1[jn * 4 + 3] * e3 + bo1[jn], 0.f);
        for (int jn = 0; jn < 64; ++jn) {
            float acc = bo2[jn];
            for (int in2 = 0; in2 < 64; ++in2) acc += Wo2[jn * 64 + in2] * u1[in2];
            u2[jn] = fmaxf(acc, 0.f);
        }
        float ox = bo3[0], oy = bo3[1];
        for (int jn = 0; jn < 64; ++jn) {
            ox += Wo3[jn] * u2[jn];
            oy += Wo3[64 + jn] * u2[jn];
        }
        // sample constants: py = si + (m2 + oy), px = sj + (m3 + ox)
        float cy = m2 + oy, cx = m3 + ox;
        float Y0 = floorf(cy), X0 = floorf(cx);
        int chi = t & 31, half = t >> 5;
        g_samp[(chi * 2 + half) * NPH + p] = make_float4(Y0, X0, cy - Y0, cx - X0);
    }

    // ---- routing_1: v1 = relu(Wr1 @ emb + br1)   (reuse s_a)
    {
        float b_ = br1[t];
        float r0 = b_, r1 = b_, r2 = b_, r3 = b_;
        for (int ch = 0; ch < 64; ++ch) {
            float wv = Wr1[t * 64 + ch];
            r0 += wv * s_b[ch][0]; r1 += wv * s_b[ch][1];
            r2 += wv * s_b[ch][2]; r3 += wv * s_b[ch][3];
        }
        __syncthreads();   // everyone done reading s_a (t1) long ago; safe to overwrite
        s_a[t][0] = fmaxf(r0, 0.f); s_a[t][1] = fmaxf(r1, 0.f);
        s_a[t][2] = fmaxf(r2, 0.f); s_a[t][3] = fmaxf(r3, 0.f);
    }
    __syncthreads();
    if (t < 4) {
        float acc = br2[0];
        for (int o = 0; o < 64; ++o) acc += Wr2[o] * s_a[o][t];
        s_r[t] = sigmoidf_(acc);
    }
    __syncthreads();

    // ---- routing_2: 4 -> 64 -> 64 -> E, sigmoid
    {
        float q = bq1[t];
        for (int f = 0; f < 4; ++f) q += Wq1[t * 4 + f] * s_r[f];
        s_q1[t] = fmaxf(q, 0.f);
    }
    __syncthreads();
    {
        float q = bq2[t];
        for (int o = 0; o < 64; ++o) q += Wq2[t * 64 + o] * s_q1[o];
        s_q2[t] = fmaxf(q, 0.f);
    }
    __syncthreads();
    if (t < 4) {
        float acc = bq3[t];
        for (int o = 0; o < 64; ++o) acc += Wq3[t * 64 + o] * s_q2[o];
        s_rw[t] = sigmoidf_(acc);
    }
    __syncthreads();

    // ---- expert-mixed compress/expand matrices for this phase
    {
        float w0 = s_rw[0], w1 = s_rw[1], w2 = s_rw[2], w3 = s_rw[3];
        int chi = t & 31, half = t >> 5;
        for (int k = 0; k < KK; ++k) {
            int gi = k * 64 + t;     // wc[e][k][ch], e-stride 512
            g_Wcm[((k * 32 + chi) * 2 + half) * NPH + p] =
                w0 * wc[gi] + w1 * wc[512 + gi] + w2 * wc[1024 + gi] + w3 * wc[1536 + gi];
            int gj = t * 8 + k;      // we[e][ch][k], e-stride 512
            g_Wem[((chi * 8 + k) * 2 + half) * NPH + p] =
                w0 * we[gj] + w1 * we[512 + gj] + w2 * we[1024 + gj] + w3 * we[1536 + gj];
        }
    }
}

// ---------------------------------------------------------------------------
// Kernel C: fused sample + per-pixel 64->8->64 expert-mixed matmul + residual.
// Lane pair (2m, 2m+1) shares one output pixel, 32 channels each;
// mid[] reduced via shfl_xor(1). Block covers 16 j-columns x 8 si-rows at a
// fixed pi phase, so only the 4 pj-phase weight slices are staged in smem.
// ---------------------------------------------------------------------------
__global__ void __launch_bounds__(256) main_kernel(const float* __restrict__ x,
                                                   float* __restrict__ out)
{
    __shared__ float  sWcm[KK * 32 * 2 * 4];   // 8KB
    __shared__ float  sWem[32 * KK * 2 * 4];   // 8KB
    __shared__ float4 sSamp[32 * 2 * 4];       // 4KB

    int pi  = blockIdx.y & 3;
    int tid = threadIdx.y * 32 + threadIdx.x;

    // stage the pi slice (pj = 0..3) of the phase tables
    const float4* gw = (const float4*)g_Wcm;
    for (int idx = tid; idx < 512; idx += 256)
        ((float4*)sWcm)[idx] = gw[idx * 4 + pi];
    const float4* ge = (const float4*)g_Wem;
    for (int idx = tid; idx < 512; idx += 256)
        ((float4*)sWem)[idx] = ge[idx * 4 + pi];
    {
        int idx = tid;
        if (idx < 256) sSamp[idx] = g_samp[(idx >> 2) * NPH + pi * 4 + (idx & 3)];
    }
    __syncthreads();

    int lane = threadIdx.x;
    int half = lane & 1;
    int m    = lane >> 1;
    int j    = blockIdx.x * 16 + m;
    int pj   = j & 3;
    int sj   = j >> 2;
    int si   = (blockIdx.y >> 2) * 8 + threadIdx.y;
    int i    = si * 4 + pi;
    int b    = blockIdx.z;

    const float* xb = x + (size_t)(b * Cc + half * 32) * (Hh * Ww);

    float fea[32];
#pragma unroll
    for (int chi = 0; chi < 32; ++chi) {
        float4 sp = sSamp[(chi * 2 + half) * 4 + pj];
        int   iy = si + (int)sp.x;
        int   ix = sj + (int)sp.y;
        float wy = sp.z, wx = sp.w;
        const float* img = xb + chi * (Hh * Ww);
        bool vy0 = ((unsigned)iy       < (unsigned)Hh);
        bool vy1 = ((unsigned)(iy + 1) < (unsigned)Hh);
        bool vx0 = ((unsigned)ix       < (unsigned)Ww);
        bool vx1 = ((unsigned)(ix + 1) < (unsigned)Ww);
        int o00 = iy * Ww + ix;
        float g00 = (vy0 & vx0) ? __ldg(img + o00)          : 0.f;
        float g01 = (vy0 & vx1) ? __ldg(img + o00 + 1)      : 0.f;
        float g10 = (vy1 & vx0) ? __ldg(img + o00 + Ww)     : 0.f;
        float g11 = (vy1 & vx1) ? __ldg(img + o00 + Ww + 1) : 0.f;
        float t0 = g00 + wx * (g01 - g00);
        float t1 = g10 + wx * (g11 - g10);
        fea[chi] = t0 + wy * (t1 - t0);
    }

    float mid[KK];
#pragma unroll
    for (int k = 0; k < KK; ++k) {
        float acc = 0.f;
#pragma unroll
        for (int chi = 0; chi < 32; ++chi)
            acc += sWcm[((k * 32 + chi) * 2 + half) * 4 + pj] * fea[chi];
        mid[k] = acc + __shfl_xor_sync(0xffffffffu, acc, 1);  // combine channel halves
    }

    float* op = out + ((size_t)(b * Cc + half * 32) * HS + i) * WS + j;
#pragma unroll
    for (int chi = 0; chi < 32; ++chi) {
        float acc = fea[chi];
#pragma unroll
        for (int k = 0; k < KK; ++k)
            acc += sWem[((chi * 8 + k) * 2 + half) * 4 + pj] * mid[k];
        op[(size_t)chi * HS * WS] = acc;
    }
}

// ---------------------------------------------------------------------------
extern "C" void kernel_launch(void* const* d_in, const int* in_sizes, int n_in,
                              void* d_out, int out_size) {
    const float* x   = (const float*)d_in[0];
    const float* wc  = (const float*)d_in[1];
    const float* we  = (const float*)d_in[2];
    const float* Wb1 = (const float*)d_in[3];
    const float* bb1 = (const float*)d_in[4];
    const float* Wb2 = (const float*)d_in[5];
    const float* bb2 = (const float*)d_in[6];
    const float* Wr1 = (const float*)d_in[7];
    const float* br1 = (const float*)d_in[8];
    const float* Wr2 = (const float*)d_in[9];
    const float* br2 = (const float*)d_in[10];
    const float* Wq1 = (const float*)d_in[11];
    const float* bq1 = (const float*)d_in[12];
    const float* Wq2 = (const float*)d_in[13];
    const float* bq2 = (const float*)d_in[14];
    const float* Wq3 = (const float*)d_in[15];
    const float* bq3 = (const float*)d_in[16];
    const float* Wo1 = (const float*)d_in[17];
    const float* bo1 = (const float*)d_in[18];
    const float* Wo2 = (const float*)d_in[19];
    const float* bo2 = (const float*)d_in[20];
    const float* Wo3 = (const float*)d_in[21];
    const float* bo3 = (const float*)d_in[22];
    // d_in[23] = scale (hardcoded 4)

    mean_kernel<<<Cc, 256>>>(x);
    phase_kernel<<<NPH, 64>>>(wc, we, Wb1, bb1, Wb2, bb2, Wr1, br1, Wr2, br2,
                              Wq1, bq1, Wq2, bq2, Wq3, bq3,
                              Wo1, bo1, Wo2, bo2, Wo3, bo3);
    dim3 grid(WS / 16, 32, BSz);   // 16 x 32 x 4 = 2048 blocks
    main_kernel<<<grid, dim3(32, 8)>>>(x, (float*)d_out);
}

// round 3
// speedup vs baseline: 2.1331x; 2.1331x over previous
#include <cuda_runtime.h>
#include <math.h>

#define Cc   64
#define Hh   64
#define Ww   64
#define BSz  4
#define HS   256
#define WS   256
#define KK   8
#define NPH  16

// ---- device scratch (no allocations allowed) ----
__device__ float g_part[256];                         // per (b,ch) partial sums
__device__ __align__(16) float g_Wcm[4 * 2048];       // [pi][k][ch4][pj][4(ch%4)]
__device__ __align__(16) float g_Wem[4 * 2048];       // [pi][ch][k4][pj][4(k%4)]
__device__ float4 g_sampA[4 * 256];                   // [pi][ch][pj]: {Y0bits,X0bits,w00,w01}
__device__ float2 g_sampW[4 * 256];                   // [pi][ch][pj]: {w10,w11}

// ---------------------------------------------------------------------------
// Kernel A: partial per-(b,ch) sums of x. grid=256, block=128.
// ---------------------------------------------------------------------------
__global__ void mean_kernel(const float* __restrict__ x) {
    int bid = blockIdx.x;                // = b*64 + ch
    const float4* p = (const float4*)(x + (size_t)bid * 4096);
    float s = 0.f;
    for (int idx = threadIdx.x; idx < 1024; idx += 128) {
        float4 v = p[idx];
        s += (v.x + v.y) + (v.z + v.w);
    }
#pragma unroll
    for (int o = 16; o > 0; o >>= 1) s += __shfl_xor_sync(0xffffffffu, s, o);
    __shared__ float red[4];
    if ((threadIdx.x & 31) == 0) red[threadIdx.x >> 5] = s;
    __syncthreads();
    if (threadIdx.x == 0)
        g_part[bid] = (red[0] + red[1]) + (red[2] + red[3]);
}

__device__ __forceinline__ float sigmoidf_(float v) { return 1.f / (1.f + expf(-v)); }

// ---------------------------------------------------------------------------
// Kernel B: per-phase meta network. 16 blocks x 256 threads.
// Everything depends only on the 16 spatial phases (i%4, j%4).
// ---------------------------------------------------------------------------
__global__ void __launch_bounds__(256) phase_kernel(
    const float* __restrict__ wc,  const float* __restrict__ we,
    const float* __restrict__ Wb1, const float* __restrict__ bb1,
    const float* __restrict__ Wb2, const float* __restrict__ bb2,
    const float* __restrict__ Wr1, const float* __restrict__ br1,
    const float* __restrict__ Wr2, const float* __restrict__ br2,
    const float* __restrict__ Wq1, const float* __restrict__ bq1,
    const float* __restrict__ Wq2, const float* __restrict__ bq2,
    const float* __restrict__ Wq3, const float* __restrict__ bq3,
    const float* __restrict__ Wo1, const float* __restrict__ bo1,
    const float* __restrict__ Wo2, const float* __restrict__ bo2,
    const float* __restrict__ Wo3, const float* __restrict__ bo3)
{
    int p = blockIdx.x, pi = p >> 2, pj = p & 3;
    int t = threadIdx.x;  // 0..255
    float m2 = (pi + 0.5f) * 0.25f - 0.5f;
    float m3 = (pj + 0.5f) * 0.25f - 0.5f;

    __shared__ float s_mean[64];
    __shared__ float s_a[64][4];
    __shared__ float s_b[64][4];
    __shared__ float s_u1[64][65];
    __shared__ float s_u2[64][65];
    __shared__ float s_r[4], s_q1[64], s_q2[64], s_rw[4];

    if (t < 64)
        s_mean[t] = (g_part[t] + g_part[64 + t] + g_part[128 + t] + g_part[192 + t])
                    * (1.f / 16384.f);
    __syncthreads();

    // body layer 1 (inp[ch] = {mean, 1/4, m2, m3})
    if (t < 64) {
        float sm = 0.f, sr = 0.f;
        for (int ch = 0; ch < 64; ++ch) {
            float wv = __ldg(Wb1 + t * 64 + ch);
            sm += wv * s_mean[ch];
            sr += wv;
        }
        float b1 = bb1[t];
        s_a[t][0] = fmaxf(sm + b1, 0.f);
        s_a[t][1] = fmaxf(0.25f * sr + b1, 0.f);
        s_a[t][2] = fmaxf(m2 * sr + b1, 0.f);
        s_a[t][3] = fmaxf(m3 * sr + b1, 0.f);
    }
    __syncthreads();

    // body layer 2 -> emb
    if (t < 64) {
        float b2 = bb2[t];
        float a0 = b2, a1 = b2, a2 = b2, a3 = b2;
        for (int ch = 0; ch < 64; ++ch) {
            float wv = __ldg(Wb2 + t * 64 + ch);
            a0 += wv * s_a[ch][0]; a1 += wv * s_a[ch][1];
            a2 += wv * s_a[ch][2]; a3 += wv * s_a[ch][3];
        }
        s_b[t][0] = fmaxf(a0, 0.f); s_b[t][1] = fmaxf(a1, 0.f);
        s_b[t][2] = fmaxf(a2, 0.f); s_b[t][3] = fmaxf(a3, 0.f);
    }
    __syncthreads();

    // ---- offset head, cooperative: thread = (ch = t>>2, q = t&3)
    {
        int ch = t >> 2, q = t & 3;
        float e0 = s_b[ch][0], e1 = s_b[ch][1], e2 = s_b[ch][2], e3 = s_b[ch][3];
        for (int s = 0; s < 16; ++s) {
            int jn = q * 16 + s;
            s_u1[ch][jn] = fmaxf(__ldg(Wo1 + jn * 4 + 0) * e0 + __ldg(Wo1 + jn * 4 + 1) * e1 +
                                 __ldg(Wo1 + jn * 4 + 2) * e2 + __ldg(Wo1 + jn * 4 + 3) * e3 +
                                 __ldg(bo1 + jn), 0.f);
        }
    }
    __syncthreads();
    {
        int ch = t >> 2, q = t & 3;
        for (int s = 0; s < 16; ++s) {
            int jn = q * 16 + s;
            float acc = __ldg(bo2 + jn);
            for (int i2 = 0; i2 < 64; ++i2)
                acc += __ldg(Wo2 + jn * 64 + i2) * s_u1[ch][i2];
            s_u2[ch][jn] = fmaxf(acc, 0.f);
        }
    }
    __syncthreads();
    if (t < 64) {
        float ox = bo3[0], oy = bo3[1];
        for (int jn = 0; jn < 64; ++jn) {
            float u = s_u2[t][jn];
            ox += __ldg(Wo3 + jn) * u;
            oy += __ldg(Wo3 + 64 + jn) * u;
        }
        float cy = m2 + oy, cx = m3 + ox;
        float Y0 = floorf(cy), X0 = floorf(cx);
        float wy = cy - Y0, wx = cx - X0;
        float omy = 1.f - wy, omx = 1.f - wx;
        g_sampA[pi * 256 + t * 4 + pj] =
            make_float4(__int_as_float((int)Y0), __int_as_float((int)X0), omy * omx, omy * wx);
        g_sampW[pi * 256 + t * 4 + pj] = make_float2(wy * omx, wy * wx);
    }

    // ---- routing_1 (reuses s_a — its readers finished before the last sync chain)
    if (t < 64) {
        float b_ = br1[t];
        float r0 = b_, r1 = b_, r2 = b_, r3 = b_;
        for (int ch = 0; ch < 64; ++ch) {
            float wv = __ldg(Wr1 + t * 64 + ch);
            r0 += wv * s_b[ch][0]; r1 += wv * s_b[ch][1];
            r2 += wv * s_b[ch][2]; r3 += wv * s_b[ch][3];
        }
        s_a[t][0] = fmaxf(r0, 0.f); s_a[t][1] = fmaxf(r1, 0.f);
        s_a[t][2] = fmaxf(r2, 0.f); s_a[t][3] = fmaxf(r3, 0.f);
    }
    __syncthreads();
    if (t < 4) {
        float acc = br2[0];
        for (int o = 0; o < 64; ++o) acc += __ldg(Wr2 + o) * s_a[o][t];
        s_r[t] = sigmoidf_(acc);
    }
    __syncthreads();
    if (t < 64) {
        float q = bq1[t];
        for (int f = 0; f < 4; ++f) q += __ldg(Wq1 + t * 4 + f) * s_r[f];
        s_q1[t] = fmaxf(q, 0.f);
    }
    __syncthreads();
    if (t < 64) {
        float q = bq2[t];
        for (int o = 0; o < 64; ++o) q += __ldg(Wq2 + t * 64 + o) * s_q1[o];
        s_q2[t] = fmaxf(q, 0.f);
    }
    __syncthreads();
    if (t < 4) {
        float acc = bq3[t];
        for (int o = 0; o < 64; ++o) acc += __ldg(Wq3 + t * 64 + o) * s_q2[o];
        s_rw[t] = sigmoidf_(acc);
    }
    __syncthreads();

    // ---- expert-mixed compress/expand matrices for this phase
    if (t < 64) {
        float w0 = s_rw[0], w1 = s_rw[1], w2 = s_rw[2], w3 = s_rw[3];
        for (int k = 0; k < KK; ++k) {
            int gi = k * 64 + t;     // wc[e][k][ch], e-stride 512
            g_Wcm[pi * 2048 + ((k * 16 + (t >> 2)) * 4 + pj) * 4 + (t & 3)] =
                w0 * wc[gi] + w1 * wc[512 + gi] + w2 * wc[1024 + gi] + w3 * wc[1536 + gi];
            int gj = t * 8 + k;      // we[e][ch][k], e-stride 512
            g_Wem[pi * 2048 + ((t * 2 + (k >> 2)) * 4 + pj) * 4 + (k & 3)] =
                w0 * we[gj] + w1 * we[512 + gj] + w2 * we[1024 + gj] + w3 * we[1536 + gj];
        }
    }
}

// ---------------------------------------------------------------------------
// Kernel C: fused sample + per-pixel 64->8->64 matmul + residual.
// One thread = one output pixel, all 64 channels. Lanes = 32 consecutive j,
// so only 4 distinct pj per warp: every weight LDS.128 touches 64B (1 phase),
// and global stores are fully coalesced. No shuffles needed.
// ---------------------------------------------------------------------------
__global__ void __launch_bounds__(256, 2) main_kernel(const float* __restrict__ x,
                                                      float* __restrict__ out)
{
    __shared__ float4 sWcm[512];     // 8KB  [k][ch4][pj]
    __shared__ float4 sWem[512];     // 8KB  [ch][k4][pj]
    __shared__ float4 sSampA[256];   // 4KB  [ch][pj]
    __shared__ float2 sSampW[256];   // 2KB  [ch][pj]

    int pi  = blockIdx.y & 3;
    int tid = threadIdx.y * 32 + threadIdx.x;
    {
        const float4* gc = ((const float4*)g_Wcm) + pi * 512;
        const float4* ge = ((const float4*)g_Wem) + pi * 512;
        sWcm[tid]       = gc[tid];
        sWcm[tid + 256] = gc[tid + 256];
        sWem[tid]       = ge[tid];
        sWem[tid + 256] = ge[tid + 256];
        sSampA[tid] = g_sampA[pi * 256 + tid];
        sSampW[tid] = g_sampW[pi * 256 + tid];
    }
    __syncthreads();

    int lane = threadIdx.x;
    int j  = blockIdx.x * 32 + lane;
    int pj = lane & 3;
    int sj = j >> 2;
    int si = (blockIdx.y >> 2) * 8 + threadIdx.y;
    int i  = si * 4 + pi;
    int b  = blockIdx.z;

    const float* xb = x + (size_t)b * (Cc * Hh * Ww);

    float fea[64];
#pragma unroll
    for (int ch = 0; ch < 64; ++ch) {
        float4 sa = sSampA[ch * 4 + pj];
        float2 sw = sSampW[ch * 4 + pj];
        int iy = si + __float_as_int(sa.x);
        int ix = sj + __float_as_int(sa.y);
        const float* img = xb + ch * (Hh * Ww);
        bool vy0 = ((unsigned)iy       < (unsigned)Hh);
        bool vy1 = ((unsigned)(iy + 1) < (unsigned)Hh);
        bool vx0 = ((unsigned)ix       < (unsigned)Ww);
        bool vx1 = ((unsigned)(ix + 1) < (unsigned)Ww);
        int o = iy * Ww + ix;
        float g00 = (vy0 & vx0) ? __ldg(img + o)          : 0.f;
        float g01 = (vy0 & vx1) ? __ldg(img + o + 1)      : 0.f;
        float g10 = (vy1 & vx0) ? __ldg(img + o + Ww)     : 0.f;
        float g11 = (vy1 & vx1) ? __ldg(img + o + Ww + 1) : 0.f;
        fea[ch] = g00 * sa.z + g01 * sa.w + g10 * sw.x + g11 * sw.y;
    }

    float mid[KK];
#pragma unroll
    for (int k = 0; k < KK; ++k) {
        float acc = 0.f;
#pragma unroll
        for (int c4 = 0; c4 < 16; ++c4) {
            float4 w = sWcm[(k * 16 + c4) * 4 + pj];
            acc += w.x * fea[4 * c4]     + w.y * fea[4 * c4 + 1]
                 + w.z * fea[4 * c4 + 2] + w.w * fea[4 * c4 + 3];
        }
        mid[k] = acc;
    }

    float* op = out + (size_t)b * (Cc * HS * WS) + i * WS + j;
#pragma unroll
    for (int ch = 0; ch < 64; ++ch) {
        float4 wa = sWem[(ch * 2 + 0) * 4 + pj];
        float4 wb = sWem[(ch * 2 + 1) * 4 + pj];
        float acc = fea[ch];
        acc += wa.x * mid[0] + wa.y * mid[1] + wa.z * mid[2] + wa.w * mid[3];
        acc += wb.x * mid[4] + wb.y * mid[5] + wb.z * mid[6] + wb.w * mid[7];
        op[(size_t)ch * (HS * WS)] = acc;
    }
}

// ---------------------------------------------------------------------------
extern "C" void kernel_launch(void* const* d_in, const int* in_sizes, int n_in,
                              void* d_out, int out_size) {
    const float* x   = (const float*)d_in[0];
    const float* wc  = (const float*)d_in[1];
    const float* we  = (const float*)d_in[2];
    const float* Wb1 = (const float*)d_in[3];
    const float* bb1 = (const float*)d_in[4];
    const float* Wb2 = (const float*)d_in[5];
    const float* bb2 = (const float*)d_in[6];
    const float* Wr1 = (const float*)d_in[7];
    const float* br1 = (const float*)d_in[8];
    const float* Wr2 = (const float*)d_in[9];
    const float* br2 = (const float*)d_in[10];
    const float* Wq1 = (const float*)d_in[11];
    const float* bq1 = (const float*)d_in[12];
    const float* Wq2 = (const float*)d_in[13];
    const float* bq2 = (const float*)d_in[14];
    const float* Wq3 = (const float*)d_in[15];
    const float* bq3 = (const float*)d_in[16];
    const float* Wo1 = (const float*)d_in[17];
    const float* bo1 = (const float*)d_in[18];
    const float* Wo2 = (const float*)d_in[19];
    const float* bo2 = (const float*)d_in[20];
    const float* Wo3 = (const float*)d_in[21];
    const float* bo3 = (const float*)d_in[22];
    // d_in[23] = scale (4)

    mean_kernel<<<256, 128>>>(x);
    phase_kernel<<<NPH, 256>>>(wc, we, Wb1, bb1, Wb2, bb2, Wr1, br1, Wr2, br2,
                               Wq1, bq1, Wq2, bq2, Wq3, bq3,
                               Wo1, bo1, Wo2, bo2, Wo3, bo3);
    dim3 grid(WS / 32, 32, BSz);   // 8 x 32 x 4 = 1024 blocks
    main_kernel<<<grid, dim3(32, 8)>>>(x, (float*)d_out);
}